// round 15
// baseline (speedup 1.0000x reference)
#include <cuda_runtime.h>
#include <cuda.h>
#include <cuda_bf16.h>
#include <cstdint>

#define DIM  1024
#define HID  2048
#define NE   4
#define NTOK 4096

#define TM 128                   // rows per CTA (both gemms)

// ---- GEMM1: cg2 M=256 x N=256, TK=32 (SW64), 3 stages, 2 CTA/SM
#define TN1 256
#define TK1 32
#define NSTAGE1 3
#define STAGE1 32768             // Ahi 8K + Alo 8K + Bhi 8K + Blo 8K (per CTA)
#define A_HI1 0
#define A_LO1 8192
#define B_HI1 16384
#define B_LO1 24576
#define SMEM1_BYTES (1024 + NSTAGE1 * STAGE1)
#define TMEM1_COLS 256

// ---- GEMM2: cg2 M=256 x N=128, TK=64 (SW128), 2 stages, 2 CTA/SM (R13 proven)
#define TN2 128
#define TK2 64
#define NSTAGE2 2
#define STAGE2 49152             // Ahi 16K + Alo 16K + Bhi 8K + Blo 8K
#define A_HI2 0
#define A_LO2 16384
#define B_HI2 32768
#define B_LO2 40960
#define SMEM2_BYTES (1024 + NSTAGE2 * STAGE2)
#define TMEM2_COLS 128

// fallback tiles
#define BM 128
#define BN 128
#define BK 16

#if defined(__CUDA_ARCH__) && defined(__CUDA_ARCH_FEAT_SM103_ALL)
#define HAS_TC 1
#else
#define HAS_TC 0
#endif

// ---------------------------------------------------------------------------
// Scratch (static __device__, allocation-free)
// ---------------------------------------------------------------------------
__device__ __nv_bfloat16 g_x_hi[(size_t)NTOK * DIM];
__device__ __nv_bfloat16 g_x_lo[(size_t)NTOK * DIM];
__device__ __nv_bfloat16 g_w1t_hi[(size_t)NE * HID * DIM];  // [e][n][k]
__device__ __nv_bfloat16 g_w1t_lo[(size_t)NE * HID * DIM];
__device__ __nv_bfloat16 g_w2t_hi[(size_t)NE * DIM * HID];  // [e][n][k]
__device__ __nv_bfloat16 g_w2t_lo[(size_t)NE * DIM * HID];
__device__ __nv_bfloat16 g_h_hi[(size_t)NE * NTOK * HID];   // router-weighted gelu(h)
__device__ __nv_bfloat16 g_h_lo[(size_t)NE * NTOK * HID];
__device__ float g_h32[(size_t)NE * NTOK * HID];            // fallback path scratch
__device__ float g_w[NTOK * NE];

// ---------------------------------------------------------------------------
// Common helpers
// ---------------------------------------------------------------------------
__device__ __forceinline__ float gelu_exact(float v) {
    return 0.5f * v * (1.0f + erff(v * 0.70710678118654752f));
}

__device__ __forceinline__ void split2(float v, __nv_bfloat16& h, __nv_bfloat16& l) {
    h = __float2bfloat16(v);
    l = __float2bfloat16(v - __bfloat162float(h));
}

__device__ __forceinline__ unsigned long long dup2(float a) {
    unsigned long long r;
    unsigned int au = __float_as_uint(a);
    asm("mov.b64 %0, {%1, %1};" : "=l"(r) : "r"(au));
    return r;
}

#define FFMA2(c, a, b) \
    asm("fma.rn.f32x2 %0, %1, %2, %0;" : "+l"(c) : "l"(a), "l"(b))

__device__ __forceinline__ uint32_t smem_u32(const void* p) {
    uint32_t a;
    asm("{ .reg .u64 t; cvta.to.shared.u64 t, %1; cvt.u32.u64 %0, t; }"
        : "=r"(a) : "l"(p));
    return a;
}

#define MBAR_INIT(a, n) \
    asm volatile("mbarrier.init.shared.b64 [%0], %1;" :: "r"(a), "r"(n) : "memory")

#define MBAR_EXPECT(a, n) \
    asm volatile("mbarrier.arrive.expect_tx.shared.b64 _, [%0], %1;" \
                 :: "r"(a), "r"(n) : "memory")

#define MBAR_WAIT(a, ph) do {                                                   \
    uint32_t _m = (a), _p = (ph), _d;                                           \
    asm volatile("{\n\t.reg .pred p;\n\t"                                       \
        "mbarrier.try_wait.parity.acquire.cta.shared::cta.b64 p, [%1], %2;\n\t" \
        "selp.b32 %0, 1, 0, p;\n\t}"                                            \
        : "=r"(_d) : "r"(_m), "r"(_p) : "memory");                              \
    if (!_d) {                                                                  \
        asm volatile("{\n\t.reg .pred P1;\n\t"                                  \
            "W_%=:\n\t"                                                         \
            "mbarrier.try_wait.parity.acquire.cta.shared::cta.b64 P1, [%0], %1, 0x989680;\n\t" \
            "@P1 bra.uni D_%=;\n\t"                                             \
            "bra.uni W_%=;\n\t"                                                 \
            "D_%=:\n\t}" :: "r"(_m), "r"(_p) : "memory");                       \
    }                                                                           \
} while (0)

#define FENCE_ASYNC() asm volatile("fence.proxy.async.shared::cta;" ::: "memory")

#define CLUSTER_SYNC_() do { \
    asm volatile("barrier.cluster.arrive.aligned;" ::: "memory"); \
    asm volatile("barrier.cluster.wait.aligned;" ::: "memory"); \
} while (0)

// ---------------------------------------------------------------------------
// tcgen05 / TMA helpers (only in the compute_103a device pass)
// ---------------------------------------------------------------------------
#if HAS_TC
// K-major SW128: layout=2, SBO=64, LBO=1
__device__ __forceinline__ uint64_t make_desc128(uint32_t addr) {
    const uint64_t base = (uint64_t(2) << 61) | (uint64_t(1) << 46)
                        | (uint64_t(64) << 32) | (uint64_t(1) << 16);
    return base | ((uint64_t)(addr >> 4) & 0x3FFF);
}
// K-major SW64: layout=4, SBO=32, LBO=1 (verified R11)
__device__ __forceinline__ uint64_t make_desc64(uint32_t addr) {
    const uint64_t base = (uint64_t(4) << 61) | (uint64_t(1) << 46)
                        | (uint64_t(32) << 32) | (uint64_t(1) << 16);
    return base | ((uint64_t)(addr >> 4) & 0x3FFF);
}

#define TC_ALLOC_CG2(sa, n) \
    asm volatile("tcgen05.alloc.cta_group::2.sync.aligned.shared::cta.b32 [%0], %1;" \
                 :: "r"(sa), "r"(n) : "memory")
#define TC_RELINQ_CG2() \
    asm volatile("tcgen05.relinquish_alloc_permit.cta_group::2.sync.aligned;")
#define TC_DEALLOC_CG2(t, n) \
    asm volatile("tcgen05.dealloc.cta_group::2.sync.aligned.b32 %0, %1;" :: "r"(t), "r"(n))
#define TC_COMMIT_MC2(mb) \
    asm volatile("tcgen05.commit.cta_group::2.mbarrier::arrive::one.shared::cluster.multicast::cluster.b64 [%0], %1;" \
                 :: "r"(mb), "h"((uint16_t)3) : "memory")
#define TC_FENCE_AFTER()  asm volatile("tcgen05.fence::after_thread_sync;" ::: "memory")
#define TC_FENCE_BEFORE() asm volatile("tcgen05.fence::before_thread_sync;" ::: "memory")
#define TC_WAIT_LD()      asm volatile("tcgen05.wait::ld.sync.aligned;" ::: "memory")

// cg2 TMA: both CTAs execute; complete_tx targets leader (bit24 cleared) barrier
#define TMA_CG2(sa, mp, cx, cy, mb) \
    asm volatile("{\n\t.reg .b32 lb;\n\t" \
        "and.b32 lb, %4, 0xFEFFFFFF;\n\t" \
        "cp.async.bulk.tensor.3d.cta_group::2.shared::cluster.global.tile.mbarrier::complete_tx::bytes " \
        "[%0], [%1, {%2, %3, %5}], [lb];\n\t}" \
        :: "r"(sa), "l"(mp), "r"(cx), "r"(cy), "r"(mb), "r"(0) : "memory")

#define TC_LD_X32(r, ta) \
    asm volatile( \
        "tcgen05.ld.sync.aligned.32x32b.x32.b32 " \
        "{%0, %1, %2, %3, %4, %5, %6, %7, " \
        " %8, %9, %10, %11, %12, %13, %14, %15, " \
        " %16, %17, %18, %19, %20, %21, %22, %23, " \
        " %24, %25, %26, %27, %28, %29, %30, %31}, [%32];" \
        : "=r"((r)[0]),  "=r"((r)[1]),  "=r"((r)[2]),  "=r"((r)[3]), \
          "=r"((r)[4]),  "=r"((r)[5]),  "=r"((r)[6]),  "=r"((r)[7]), \
          "=r"((r)[8]),  "=r"((r)[9]),  "=r"((r)[10]), "=r"((r)[11]), \
          "=r"((r)[12]), "=r"((r)[13]), "=r"((r)[14]), "=r"((r)[15]), \
          "=r"((r)[16]), "=r"((r)[17]), "=r"((r)[18]), "=r"((r)[19]), \
          "=r"((r)[20]), "=r"((r)[21]), "=r"((r)[22]), "=r"((r)[23]), \
          "=r"((r)[24]), "=r"((r)[25]), "=r"((r)[26]), "=r"((r)[27]), \
          "=r"((r)[28]), "=r"((r)[29]), "=r"((r)[30]), "=r"((r)[31]) \
        : "r"(ta))

__device__ __forceinline__ void mma_ss_cg2(uint32_t d, uint64_t ad, uint64_t bd,
                                           uint32_t idesc, bool acc) {
    uint32_t en = acc ? 1u : 0u;
    asm volatile(
        "{\n\t.reg .pred p;\n\t"
        "setp.ne.u32 p, %5, 0;\n\t"
        "tcgen05.mma.cta_group::2.kind::f16 [%0], %1, %2, %3, "
        "{%4, %4, %4, %4, %4, %4, %4, %4}, p;\n\t}"
        :: "r"(d), "l"(ad), "l"(bd), "r"(idesc), "r"(0u), "r"(en)
        : "memory");
}

#define IDESC1 ((1u << 4) | (1u << 7) | (1u << 10) | ((TN1 / 8) << 17) | (16u << 24))
#define IDESC2 ((1u << 4) | (1u << 7) | (1u << 10) | ((TN2 / 8) << 17) | (16u << 24))

#define FULL_B(s) (sb + (s) * 8)
#define DONE_B(s) (sb + 24 + (s) * 8)

__device__ __forceinline__ void issue_chunk_g1(uint32_t tmem, uint32_t stp32, bool first) {
    uint64_t dAh = make_desc64(stp32 + A_HI1);
    uint64_t dAl = make_desc64(stp32 + A_LO1);
    uint64_t dBh = make_desc64(stp32 + B_HI1);
    uint64_t dBl = make_desc64(stp32 + B_LO1);
    #pragma unroll
    for (int k = 0; k < 2; ++k) {            // TK=32 -> 2 K=16 steps
        mma_ss_cg2(tmem, dAh + 2 * k, dBh + 2 * k, IDESC1, !(first && k == 0));
        mma_ss_cg2(tmem, dAh + 2 * k, dBl + 2 * k, IDESC1, true);
        mma_ss_cg2(tmem, dAl + 2 * k, dBh + 2 * k, IDESC1, true);
    }
}

__device__ __forceinline__ void issue_chunk_g2(uint32_t tmem, uint32_t stp32, bool first) {
    uint64_t dAh = make_desc128(stp32 + A_HI2);
    uint64_t dAl = make_desc128(stp32 + A_LO2);
    uint64_t dBh = make_desc128(stp32 + B_HI2);
    uint64_t dBl = make_desc128(stp32 + B_LO2);
    #pragma unroll
    for (int k = 0; k < 4; ++k) {            // TK=64 -> 4 K=16 steps
        mma_ss_cg2(tmem, dAh + 2 * k, dBh + 2 * k, IDESC2, !(first && k == 0));
        mma_ss_cg2(tmem, dAh + 2 * k, dBl + 2 * k, IDESC2, true);
        mma_ss_cg2(tmem, dAl + 2 * k, dBh + 2 * k, IDESC2, true);
    }
}

// TMA-fed cg2 mainloop, depth NST, stage STB. tid0 (both ranks) = TMA issuer;
// rank0 tid32 = MMA consumer. full[s]: count 1 on rank0 (expect_tx 2*STB).
// done[s]: count 1, multicast commit to both CTAs.
template <int NCHUNKS, int NST, int STB, typename FT, typename FI>
__device__ __forceinline__ void cg2_tma_mainloop(uint32_t sb, int tid,
                                                 uint32_t rank,
                                                 FT&& issue_tma, FI&& issue_mma) {
    if (tid == 0) {
        for (int c = 0; c < NCHUNKS; ++c) {
            int s = c % NST;
            if (c >= NST) MBAR_WAIT(DONE_B(s), (c / NST - 1) & 1);
            if (rank == 0) MBAR_EXPECT(FULL_B(s), 2 * STB);
            issue_tma(c, sb + 1024 + s * STB, FULL_B(s));
        }
        const int lc = NCHUNKS - 1;
        MBAR_WAIT(DONE_B(lc % NST), (lc / NST) & 1);
    } else if (rank == 0 && tid == 32) {
        for (int c = 0; c < NCHUNKS; ++c) {
            int s = c % NST;
            int u = c / NST;
            uint32_t stp32 = sb + 1024 + s * STB;
            MBAR_WAIT(FULL_B(s), u & 1);
            issue_mma(c, stp32);
            TC_COMMIT_MC2(DONE_B(s));
        }
    }
    __syncthreads();
    TC_FENCE_AFTER();
}
#endif  // HAS_TC

// ---------------------------------------------------------------------------
// Pre-pass: split x into bf16 hi/lo
// ---------------------------------------------------------------------------
__global__ void split_x_kernel(const float* __restrict__ x) {
    int i = blockIdx.x * blockDim.x + threadIdx.x;
    float4 v = ((const float4*)x)[i];
    __nv_bfloat16 h[4], l[4];
    split2(v.x, h[0], l[0]); split2(v.y, h[1], l[1]);
    split2(v.z, h[2], l[2]); split2(v.w, h[3], l[3]);
    *(uint2*)&g_x_hi[(size_t)i * 4] = *(uint2*)h;
    *(uint2*)&g_x_lo[(size_t)i * 4] = *(uint2*)l;
}

// ---------------------------------------------------------------------------
// Pre-pass: transpose + split weights.  src [e][R][C] fp32 -> dst [e][C][R] bf16
// ---------------------------------------------------------------------------
__global__ void tsplit_kernel(const float* __restrict__ src, int R, int C, int which) {
    __shared__ float tile[32][33];
    int e = blockIdx.z;
    int r0 = blockIdx.y * 32, c0 = blockIdx.x * 32;
    int tx = threadIdx.x, ty = threadIdx.y;          // 32 x 8
    const float* s = src + (size_t)e * R * C;
    #pragma unroll
    for (int i = 0; i < 4; ++i)
        tile[ty + i * 8][tx] = s[(size_t)(r0 + ty + i * 8) * C + c0 + tx];
    __syncthreads();
    __nv_bfloat16* dh = (which ? g_w2t_hi : g_w1t_hi) + (size_t)e * R * C;
    __nv_bfloat16* dl = (which ? g_w2t_lo : g_w1t_lo) + (size_t)e * R * C;
    #pragma unroll
    for (int i = 0; i < 4; ++i) {
        float v = tile[tx][ty + i * 8];
        __nv_bfloat16 h, l;
        split2(v, h, l);
        size_t o = (size_t)(c0 + ty + i * 8) * R + r0 + tx;
        dh[o] = h; dl[o] = l;
    }
}

// ---------------------------------------------------------------------------
// Router: softmax(x @ Wr + br). One warp per token.
// ---------------------------------------------------------------------------
__global__ void router_kernel(const float* __restrict__ x,
                              const float* __restrict__ Wr,
                              const float* __restrict__ br) {
    int warp = (blockIdx.x * blockDim.x + threadIdx.x) >> 5;
    int lane = threadIdx.x & 31;
    if (warp >= NTOK) return;
    const float4* xr = (const float4*)(x + (size_t)warp * DIM);
    const float4* wr = (const float4*)Wr;
    float a0 = 0.f, a1 = 0.f, a2 = 0.f, a3 = 0.f;
    #pragma unroll
    for (int p = 0; p < DIM / 128; ++p) {
        int db = p * 32 + lane;
        float4 xv = xr[db];
        float4 w;
        w = wr[db * 4 + 0];
        a0 += xv.x * w.x; a1 += xv.x * w.y; a2 += xv.x * w.z; a3 += xv.x * w.w;
        w = wr[db * 4 + 1];
        a0 += xv.y * w.x; a1 += xv.y * w.y; a2 += xv.y * w.z; a3 += xv.y * w.w;
        w = wr[db * 4 + 2];
        a0 += xv.z * w.x; a1 += xv.z * w.y; a2 += xv.z * w.z; a3 += xv.z * w.w;
        w = wr[db * 4 + 3];
        a0 += xv.w * w.x; a1 += xv.w * w.y; a2 += xv.w * w.z; a3 += xv.w * w.w;
    }
    #pragma unroll
    for (int off = 16; off; off >>= 1) {
        a0 += __shfl_xor_sync(0xffffffffu, a0, off);
        a1 += __shfl_xor_sync(0xffffffffu, a1, off);
        a2 += __shfl_xor_sync(0xffffffffu, a2, off);
        a3 += __shfl_xor_sync(0xffffffffu, a3, off);
    }
    if (lane == 0) {
        a0 += br[0]; a1 += br[1]; a2 += br[2]; a3 += br[3];
        float m = fmaxf(fmaxf(a0, a1), fmaxf(a2, a3));
        float e0 = expf(a0 - m), e1 = expf(a1 - m), e2 = expf(a2 - m), e3 = expf(a3 - m);
        float inv = 1.0f / (e0 + e1 + e2 + e3);
        *(float4*)&g_w[warp * NE] = make_float4(e0 * inv, e1 * inv, e2 * inv, e3 * inv);
    }
}

// ---------------------------------------------------------------------------
// GEMM1: D = x@W1[e] (cg2 M=256 x N=256, TK=32/SW64, TMA-fed, depth 3, 2 CTA/SM)
// epilogue h = split(w * gelu(D + b1)); grid (32, 8, 4), cluster (2,1,1)
// ---------------------------------------------------------------------------
__global__ __launch_bounds__(256, 2) __cluster_dims__(2, 1, 1)
void gemm1_kernel(const __grid_constant__ CUtensorMap mAh,
                  const __grid_constant__ CUtensorMap mAl,
                  const __grid_constant__ CUtensorMap mBh,
                  const __grid_constant__ CUtensorMap mBl,
                  const float* __restrict__ x, const float* __restrict__ W1,
                  const float* __restrict__ b1)
{
#if HAS_TC
    extern __shared__ __align__(1024) char smem[];
    uint32_t sb = smem_u32(smem);
    int tid = threadIdx.x, wid = tid >> 5, lane = tid & 31;
    uint32_t rank = (uint32_t)(blockIdx.x & 1);
    int e  = blockIdx.z;
    int t0 = blockIdx.x * TM;                        // this CTA's 128 rows
    int n0 = blockIdx.y * TN1;                       // cluster's 256 cols

    if (wid == 0) { TC_ALLOC_CG2(sb + 48, TMEM1_COLS); TC_RELINQ_CG2(); }
    __syncthreads();
    uint32_t tmem = *(volatile uint32_t*)(smem + 48);
    if (tid == 0) {
        #pragma unroll
        for (int s = 0; s < NSTAGE1; ++s) {
            MBAR_INIT(FULL_B(s), 1);
            MBAR_INIT(DONE_B(s), 1);
        }
        FENCE_ASYNC();
    }
    __syncthreads();
    CLUSTER_SYNC_();

    const int arow = t0;
    const int brow = e * HID + n0 + (int)rank * (TN1 / 2);

    cg2_tma_mainloop<DIM / TK1, NSTAGE1, STAGE1>(sb, tid, rank,
        [&](int c, uint32_t stp32, uint32_t mb) {
            int k0 = c * TK1;
            TMA_CG2(stp32 + A_HI1, &mAh, k0, arow, mb);
            TMA_CG2(stp32 + A_LO1, &mAl, k0, arow, mb);
            TMA_CG2(stp32 + B_HI1, &mBh, k0, brow, mb);
            TMA_CG2(stp32 + B_LO1, &mBl, k0, brow, mb);
        },
        [&](int c, uint32_t stp32) {
            issue_chunk_g1(tmem, stp32, c == 0);
        });

    if (wid < 4) {
        int t = t0 + wid * 32 + lane;
        float w = g_w[t * NE + e];
        const float* b1e = b1 + (size_t)e * HID + n0;
        __nv_bfloat16* hh = g_h_hi + ((size_t)e * NTOK + t) * HID + n0;
        __nv_bfloat16* hl = g_h_lo + ((size_t)e * NTOK + t) * HID + n0;
        #pragma unroll
        for (int g = 0; g < TN1 / 32; ++g) {
            uint32_t d[32];
            TC_LD_X32(d, tmem + g * 32);
            TC_WAIT_LD();
            __align__(16) __nv_bfloat16 tH[32], tL[32];
            #pragma unroll
            for (int j = 0; j < 32; ++j) {
                float v = __uint_as_float(d[j]) + b1e[g * 32 + j];
                v = gelu_exact(v) * w;
                split2(v, tH[j], tL[j]);
            }
            #pragma unroll
            for (int q = 0; q < 4; ++q) {
                ((uint4*)(hh + g * 32))[q] = ((uint4*)tH)[q];
                ((uint4*)(hl + g * 32))[q] = ((uint4*)tL)[q];
            }
        }
        TC_FENCE_BEFORE();
    }
    __syncthreads();
    if (wid == 0) TC_DEALLOC_CG2(tmem, TMEM1_COLS);
    CLUSTER_SYNC_();
#else
    const int e  = blockIdx.z;
    const int t0 = blockIdx.x * TM;
    const float* A = x;
    const float* B = W1 + (size_t)e * DIM * HID;
    float* C = g_h32 + (size_t)e * NTOK * HID;

    __shared__ float As[BK][BM];
    __shared__ float Bs[BK][BN];
    const int tid = threadIdx.x;
    const int tx = tid & 15, ty = tid >> 4;

    for (int nb = 0; nb < TN1 / BN; ++nb) {
        const int n0 = blockIdx.y * TN1 + nb * BN;
        unsigned long long acc[8][4];
        #pragma unroll
        for (int i = 0; i < 8; ++i)
            #pragma unroll
            for (int p = 0; p < 4; ++p) acc[i][p] = 0ull;

        for (int kk = 0; kk < DIM; kk += BK) {
            #pragma unroll
            for (int f = 0; f < 2; ++f) {
                int idx = tid + f * 256;
                int row = idx >> 2, q = idx & 3;
                float4 v = *(const float4*)(A + (size_t)(t0 + row) * DIM + kk + q * 4);
                As[q * 4 + 0][row] = v.x; As[q * 4 + 1][row] = v.y;
                As[q * 4 + 2][row] = v.z; As[q * 4 + 3][row] = v.w;
            }
            #pragma unroll
            for (int f = 0; f < 2; ++f) {
                int idx = tid + f * 256;
                int kr = idx >> 5, q = idx & 31;
                *(float4*)&Bs[kr][q * 4] =
                    *(const float4*)(B + (size_t)(kk + kr) * HID + n0 + q * 4);
            }
            __syncthreads();
            #pragma unroll
            for (int k = 0; k < BK; ++k) {
                float4 av0 = *(const float4*)&As[k][ty * 4];
                float4 av1 = *(const float4*)&As[k][ty * 4 + 64];
                ulonglong2 bq0 = *(const ulonglong2*)&Bs[k][tx * 4];
                ulonglong2 bq1 = *(const ulonglong2*)&Bs[k][tx * 4 + 64];
                unsigned long long bp[4] = {bq0.x, bq0.y, bq1.x, bq1.y};
                float a_s[8] = {av0.x, av0.y, av0.z, av0.w, av1.x, av1.y, av1.z, av1.w};
                unsigned long long ad[8];
                #pragma unroll
                for (int i = 0; i < 8; ++i) ad[i] = dup2(a_s[i]);
                #pragma unroll
                for (int i = 0; i < 8; ++i)
                    #pragma unroll
                    for (int p = 0; p < 4; ++p)
                        FFMA2(acc[i][p], ad[i], bp[p]);
            }
            __syncthreads();
        }

        const float* brow = b1 + (size_t)e * HID;
        #pragma unroll
        for (int i = 0; i < 8; ++i) {
            int gr = t0 + ty * 4 + (i & 3) + ((i >> 2) << 6);
            float* crow = C + (size_t)gr * HID;
            #pragma unroll
            for (int p = 0; p < 4; ++p) {
                int gc = n0 + tx * 4 + ((p >> 1) << 6) + ((p & 1) << 1);
                float lo = __uint_as_float((unsigned int)acc[i][p]);
                float hi = __uint_as_float((unsigned int)(acc[i][p] >> 32));
                crow[gc]     = gelu_exact(lo + brow[gc]);
                crow[gc + 1] = gelu_exact(hi + brow[gc + 1]);
            }
        }
        __syncthreads();
    }
#endif
}

// ---------------------------------------------------------------------------
// GEMM2: D = sum_e (w.h[e]) @ W2[e] (cg2 M=256 x N=128, TK=64/SW128, depth 2)
// out = D + sum_e w_e b2[e]; grid (32, 8), cluster (2,1,1)
// ---------------------------------------------------------------------------
__global__ __launch_bounds__(256, 2) __cluster_dims__(2, 1, 1)
void gemm2_kernel(const __grid_constant__ CUtensorMap mAh,
                  const __grid_constant__ CUtensorMap mAl,
                  const __grid_constant__ CUtensorMap mBh,
                  const __grid_constant__ CUtensorMap mBl,
                  const float* __restrict__ W2, const float* __restrict__ b2,
                  float* __restrict__ out)
{
#if HAS_TC
    extern __shared__ __align__(1024) char smem[];
    uint32_t sb = smem_u32(smem);
    int tid = threadIdx.x, wid = tid >> 5, lane = tid & 31;
    uint32_t rank = (uint32_t)(blockIdx.x & 1);
    int t0 = blockIdx.x * TM;
    int n0 = blockIdx.y * TN2;

    if (wid == 0) { TC_ALLOC_CG2(sb + 48, TMEM2_COLS); TC_RELINQ_CG2(); }
    __syncthreads();
    uint32_t tmem = *(volatile uint32_t*)(smem + 48);
    if (tid == 0) {
        #pragma unroll
        for (int s = 0; s < NSTAGE2; ++s) {
            MBAR_INIT(FULL_B(s), 1);
            MBAR_INIT(DONE_B(s), 1);
        }
        FENCE_ASYNC();
    }
    __syncthreads();
    CLUSTER_SYNC_();

    cg2_tma_mainloop<NE * HID / TK2, NSTAGE2, STAGE2>(sb, tid, rank,
        [&](int c, uint32_t stp32, uint32_t mb) {
            int e  = c >> 5;
            int k0 = (c & 31) * TK2;
            int ar = e * NTOK + t0;
            int br = e * DIM + n0 + (int)rank * (TN2 / 2);
            TMA_CG2(stp32 + A_HI2, &mAh, k0, ar, mb);
            TMA_CG2(stp32 + A_LO2, &mAl, k0, ar, mb);
            TMA_CG2(stp32 + B_HI2, &mBh, k0, br, mb);
            TMA_CG2(stp32 + B_LO2, &mBl, k0, br, mb);
        },
        [&](int c, uint32_t stp32) {
            issue_chunk_g2(tmem, stp32, c == 0);
        });

    if (wid < 4) {
        int t = t0 + wid * 32 + lane;
        float4 w4 = *(const float4*)&g_w[t * NE];
        float* orow = out + (size_t)t * DIM + n0;
        #pragma unroll
        for (int g = 0; g < TN2 / 32; ++g) {
            uint32_t d[32];
            TC_LD_X32(d, tmem + g * 32);
            TC_WAIT_LD();
            __align__(16) float tO[32];
            #pragma unroll
            for (int j = 0; j < 32; ++j) {
                int n = n0 + g * 32 + j;
                float bias = w4.x * b2[n] + w4.y * b2[DIM + n]
                           + w4.z * b2[2 * DIM + n] + w4.w * b2[3 * DIM + n];
                tO[j] = __uint_as_float(d[j]) + bias;
            }
            #pragma unroll
            for (int q = 0; q < 8; ++q)
                ((uint4*)(orow + g * 32))[q] = ((uint4*)tO)[q];
        }
        TC_FENCE_BEFORE();
    }
    __syncthreads();
    if (wid == 0) TC_DEALLOC_CG2(tmem, TMEM2_COLS);
    CLUSTER_SYNC_();
#else
    const int t0 = blockIdx.x * TM;
    __shared__ float As[BK][BM];
    __shared__ float Bs[BK][BN];
    __shared__ float ws[BM];
    const int tid = threadIdx.x;
    const int tx = tid & 15, ty = tid >> 4;

    {
        const int n0 = blockIdx.y * TN2;
        unsigned long long acc[8][4];
        #pragma unroll
        for (int i = 0; i < 8; ++i)
            #pragma unroll
            for (int p = 0; p < 4; ++p) acc[i][p] = 0ull;

        for (int e = 0; e < NE; ++e) {
            if (tid < BM) ws[tid] = g_w[(t0 + tid) * NE + e];
            __syncthreads();
            const float* A = g_h32 + (size_t)e * NTOK * HID;
            const float* B = W2 + (size_t)e * HID * DIM;

            for (int kk = 0; kk < HID; kk += BK) {
                #pragma unroll
                for (int f = 0; f < 2; ++f) {
                    int idx = tid + f * 256;
                    int row = idx >> 2, q = idx & 3;
                    float wv = ws[row];
                    float4 v = *(const float4*)(A + (size_t)(t0 + row) * HID + kk + q * 4);
                    As[q * 4 + 0][row] = v.x * wv; As[q * 4 + 1][row] = v.y * wv;
                    As[q * 4 + 2][row] = v.z * wv; As[q * 4 + 3][row] = v.w * wv;
                }
                #pragma unroll
                for (int f = 0; f < 2; ++f) {
                    int idx = tid + f * 256;
                    int kr = idx >> 5, q = idx & 31;
                    *(float4*)&Bs[kr][q * 4] =
                        *(const float4*)(B + (size_t)(kk + kr) * DIM + n0 + q * 4);
                }
                __syncthreads();
                #pragma unroll
                for (int k = 0; k < BK; ++k) {
                    float4 av0 = *(const float4*)&As[k][ty * 4];
                    float4 av1 = *(const float4*)&As[k][ty * 4 + 64];
                    ulonglong2 bq0 = *(const ulonglong2*)&Bs[k][tx * 4];
                    ulonglong2 bq1 = *(const ulonglong2*)&Bs[k][tx * 4 + 64];
                    unsigned long long bp[4] = {bq0.x, bq0.y, bq1.x, bq1.y};
                    float a_s[8] = {av0.x, av0.y, av0.z, av0.w, av1.x, av1.y, av1.z, av1.w};
                    unsigned long long ad[8];
                    #pragma unroll
                    for (int i = 0; i < 8; ++i) ad[i] = dup2(a_s[i]);
                    #pragma unroll
                    for (int i = 0; i < 8; ++i)
                        #pragma unroll
                        for (int p = 0; p < 4; ++p)
                            FFMA2(acc[i][p], ad[i], bp[p]);
                }
                __syncthreads();
            }
        }

        #pragma unroll
        for (int i = 0; i < 8; ++i) {
            int gr = t0 + ty * 4 + (i & 3) + ((i >> 2) << 6);
            float4 wv = *(const float4*)&g_w[gr * NE];
            float* crow = out + (size_t)gr * DIM;
            #pragma unroll
            for (int p = 0; p < 4; ++p) {
                int gc = n0 + tx * 4 + ((p >> 1) << 6) + ((p & 1) << 1);
                float lo = __uint_as_float((unsigned int)acc[i][p]);
                float hi = __uint_as_float((unsigned int)(acc[i][p] >> 32));
                float blo = wv.x * b2[0 * DIM + gc] + wv.y * b2[1 * DIM + gc]
                          + wv.z * b2[2 * DIM + gc] + wv.w * b2[3 * DIM + gc];
                float bhi = wv.x * b2[0 * DIM + gc + 1] + wv.y * b2[1 * DIM + gc + 1]
                          + wv.z * b2[2 * DIM + gc + 1] + wv.w * b2[3 * DIM + gc + 1];
                crow[gc]     = lo + blo;
                crow[gc + 1] = hi + bhi;
            }
        }
        __syncthreads();
    }
#endif
}

// ---------------------------------------------------------------------------
// Host-side tensormap construction (runtime entry point, no -lcuda link)
// ---------------------------------------------------------------------------
typedef CUresult (*EncodeFn)(CUtensorMap*, CUtensorMapDataType, cuuint32_t, void*,
    const cuuint64_t*, const cuuint64_t*, const cuuint32_t*, const cuuint32_t*,
    CUtensorMapInterleave, CUtensorMapSwizzle, CUtensorMapL2promotion,
    CUtensorMapFloatOOBfill);

static EncodeFn get_encode_fn() {
    static EncodeFn fn = nullptr;
    if (!fn) {
        void* p = nullptr;
        cudaDriverEntryPointQueryResult qr;
#if CUDART_VERSION >= 12050
        cudaGetDriverEntryPointByVersion("cuTensorMapEncodeTiled", &p, 12000,
                                         cudaEnableDefault, &qr);
#else
        cudaGetDriverEntryPoint("cuTensorMapEncodeTiled", &p,
                                cudaEnableDefault, &qr);
#endif
        fn = (EncodeFn)p;
    }
    return fn;
}

static void encode_map(CUtensorMap* m, void* ptr, uint64_t d0, uint64_t d1,
                       uint32_t b0, uint32_t b1, CUtensorMapSwizzle sw) {
    cuuint64_t dims[3] = {d0, d1, 1};
    cuuint64_t strides[2] = {d0 * 2, d0 * 2 * d1};
    cuuint32_t box[3] = {b0, b1, 1};
    cuuint32_t es[3] = {1, 1, 1};
    get_encode_fn()(m, CU_TENSOR_MAP_DATA_TYPE_BFLOAT16, 3, ptr, dims, strides,
                    box, es, CU_TENSOR_MAP_INTERLEAVE_NONE, sw,
                    CU_TENSOR_MAP_L2_PROMOTION_L2_128B,
                    CU_TENSOR_MAP_FLOAT_OOB_FILL_NONE);
}

// ---------------------------------------------------------------------------
extern "C" void kernel_launch(void* const* d_in, const int* in_sizes, int n_in,
                              void* d_out, int out_size) {
    const float* x  = (const float*)d_in[0];
    const float* W1 = (const float*)d_in[1];
    const float* b1 = (const float*)d_in[2];
    const float* W2 = (const float*)d_in[3];
    const float* b2 = (const float*)d_in[4];
    const float* Wr = (const float*)d_in[5];
    const float* br = (const float*)d_in[6];
    float* out = (float*)d_out;

    cudaFuncSetAttribute(gemm1_kernel, cudaFuncAttributeMaxDynamicSharedMemorySize, SMEM1_BYTES);
    cudaFuncSetAttribute(gemm2_kernel, cudaFuncAttributeMaxDynamicSharedMemorySize, SMEM2_BYTES);

    void *p_xh, *p_xl, *p_w1h, *p_w1l, *p_w2h, *p_w2l, *p_hh, *p_hl;
    cudaGetSymbolAddress(&p_xh, g_x_hi);
    cudaGetSymbolAddress(&p_xl, g_x_lo);
    cudaGetSymbolAddress(&p_w1h, g_w1t_hi);
    cudaGetSymbolAddress(&p_w1l, g_w1t_lo);
    cudaGetSymbolAddress(&p_w2h, g_w2t_hi);
    cudaGetSymbolAddress(&p_w2l, g_w2t_lo);
    cudaGetSymbolAddress(&p_hh, g_h_hi);
    cudaGetSymbolAddress(&p_hl, g_h_lo);

    CUtensorMap m1Ah, m1Al, m1Bh, m1Bl, m2Ah, m2Al, m2Bh, m2Bl;
    // GEMM1: TK=32 (64B rows) -> SWIZZLE_64B
    encode_map(&m1Ah, p_xh, DIM, NTOK, TK1, TM, CU_TENSOR_MAP_SWIZZLE_64B);
    encode_map(&m1Al, p_xl, DIM, NTOK, TK1, TM, CU_TENSOR_MAP_SWIZZLE_64B);
    encode_map(&m1Bh, p_w1h, DIM, (uint64_t)NE * HID, TK1, TN1 / 2, CU_TENSOR_MAP_SWIZZLE_64B);
    encode_map(&m1Bl, p_w1l, DIM, (uint64_t)NE * HID, TK1, TN1 / 2, CU_TENSOR_MAP_SWIZZLE_64B);
    // GEMM2: TK=64 (128B rows) -> SWIZZLE_128B
    encode_map(&m2Ah, p_hh, HID, (uint64_t)NE * NTOK, TK2, TM, CU_TENSOR_MAP_SWIZZLE_128B);
    encode_map(&m2Al, p_hl, HID, (uint64_t)NE * NTOK, TK2, TM, CU_TENSOR_MAP_SWIZZLE_128B);
    encode_map(&m2Bh, p_w2h, HID, (uint64_t)NE * DIM, TK2, TN2 / 2, CU_TENSOR_MAP_SWIZZLE_128B);
    encode_map(&m2Bl, p_w2l, HID, (uint64_t)NE * DIM, TK2, TN2 / 2, CU_TENSOR_MAP_SWIZZLE_128B);

    // gemm1 is the 4th launch (lands in the ncu -s/-c capture window).
    router_kernel<<<NTOK / 8, 256>>>(x, Wr, br);
    split_x_kernel<<<NTOK * DIM / 1024, 256>>>(x);
    {   // W1 [E][DIM][HID] -> W1T [E][HID][DIM]
        dim3 g(HID / 32, DIM / 32, NE), b(32, 8);
        tsplit_kernel<<<g, b>>>(W1, DIM, HID, 0);
    }
    {
        dim3 g(NTOK / TM, HID / TN1, NE);    // 32 x 8 x 4, clusters of 2 on x
        gemm1_kernel<<<g, 256, SMEM1_BYTES>>>(m1Ah, m1Al, m1Bh, m1Bl, x, W1, b1);
    }
    {   // W2 [E][HID][DIM] -> W2T [E][DIM][HID]  (needed only by gemm2)
        dim3 g(DIM / 32, HID / 32, NE), b(32, 8);
        tsplit_kernel<<<g, b>>>(W2, HID, DIM, 1);
    }
    {
        dim3 g(NTOK / TM, DIM / TN2);        // 32 x 8, clusters of 2 on x
        gemm2_kernel<<<g, 256, SMEM2_BYTES>>>(m2Ah, m2Al, m2Bh, m2Bl, W2, b2, out);
    }
}

// round 17
// speedup vs baseline: 1.8560x; 1.8560x over previous
#include <cuda_runtime.h>
#include <cuda.h>
#include <cuda_bf16.h>
#include <cstdint>

#define DIM  1024
#define HID  2048
#define NE   4
#define NTOK 4096

// cg2 tiles: cluster of 2 CTAs computes M=256 x N=128, 2 CTAs per SM (R13 proven)
#define TM 128                   // rows per CTA
#define TN 128                   // N per cluster tile
#define TK 64                    // K elements per chunk (128B bf16 row)
#define NSTAGE 2
#define STAGE_BYTES 49152        // Ahi 16K + Alo 16K + Bhi 8K + Blo 8K (per CTA)
#define SMEM_BYTES (1024 + NSTAGE * STAGE_BYTES)
#define TMEM_COLS 128

// Stage region offsets
#define A_HI_OFF 0
#define A_LO_OFF 16384
#define B_HI_OFF 32768
#define B_LO_OFF 40960

// fallback tiles
#define BM 128
#define BN 128
#define BK 16

#if defined(__CUDA_ARCH__) && defined(__CUDA_ARCH_FEAT_SM103_ALL)
#define HAS_TC 1
#else
#define HAS_TC 0
#endif

// ---------------------------------------------------------------------------
// Scratch (static __device__, allocation-free)
// ---------------------------------------------------------------------------
__device__ __nv_bfloat16 g_x_hi[(size_t)NTOK * DIM];
__device__ __nv_bfloat16 g_x_lo[(size_t)NTOK * DIM];
__device__ __nv_bfloat16 g_w1t_hi[(size_t)NE * HID * DIM];  // [e][n][k]
__device__ __nv_bfloat16 g_w1t_lo[(size_t)NE * HID * DIM];
__device__ __nv_bfloat16 g_w2t_hi[(size_t)NE * DIM * HID];  // [e][n][k]
__device__ __nv_bfloat16 g_w2t_lo[(size_t)NE * DIM * HID];
__device__ __nv_bfloat16 g_h_hi[(size_t)NE * NTOK * HID];   // router-weighted gelu(h)
__device__ __nv_bfloat16 g_h_lo[(size_t)NE * NTOK * HID];
__device__ float g_h32[(size_t)NE * NTOK * HID];            // fallback path scratch
__device__ float g_w[NTOK * NE];

// ---------------------------------------------------------------------------
// Common helpers
// ---------------------------------------------------------------------------
__device__ __forceinline__ float gelu_exact(float v) {
    return 0.5f * v * (1.0f + erff(v * 0.70710678118654752f));
}

__device__ __forceinline__ void split2(float v, __nv_bfloat16& h, __nv_bfloat16& l) {
    h = __float2bfloat16(v);
    l = __float2bfloat16(v - __bfloat162float(h));
}

__device__ __forceinline__ unsigned long long dup2(float a) {
    unsigned long long r;
    unsigned int au = __float_as_uint(a);
    asm("mov.b64 %0, {%1, %1};" : "=l"(r) : "r"(au));
    return r;
}

#define FFMA2(c, a, b) \
    asm("fma.rn.f32x2 %0, %1, %2, %0;" : "+l"(c) : "l"(a), "l"(b))

__device__ __forceinline__ uint32_t smem_u32(const void* p) {
    uint32_t a;
    asm("{ .reg .u64 t; cvta.to.shared.u64 t, %1; cvt.u32.u64 %0, t; }"
        : "=r"(a) : "l"(p));
    return a;
}

#define MBAR_INIT(a, n) \
    asm volatile("mbarrier.init.shared.b64 [%0], %1;" :: "r"(a), "r"(n) : "memory")

#define MBAR_EXPECT(a, n) \
    asm volatile("mbarrier.arrive.expect_tx.shared.b64 _, [%0], %1;" \
                 :: "r"(a), "r"(n) : "memory")

#define MBAR_WAIT(a, ph) do {                                                   \
    uint32_t _m = (a), _p = (ph), _d;                                           \
    asm volatile("{\n\t.reg .pred p;\n\t"                                       \
        "mbarrier.try_wait.parity.acquire.cta.shared::cta.b64 p, [%1], %2;\n\t" \
        "selp.b32 %0, 1, 0, p;\n\t}"                                            \
        : "=r"(_d) : "r"(_m), "r"(_p) : "memory");                              \
    if (!_d) {                                                                  \
        asm volatile("{\n\t.reg .pred P1;\n\t"                                  \
            "W_%=:\n\t"                                                         \
            "mbarrier.try_wait.parity.acquire.cta.shared::cta.b64 P1, [%0], %1, 0x989680;\n\t" \
            "@P1 bra.uni D_%=;\n\t"                                             \
            "bra.uni W_%=;\n\t"                                                 \
            "D_%=:\n\t}" :: "r"(_m), "r"(_p) : "memory");                       \
    }                                                                           \
} while (0)

#define FENCE_ASYNC() asm volatile("fence.proxy.async.shared::cta;" ::: "memory")

#define CLUSTER_SYNC_() do { \
    asm volatile("barrier.cluster.arrive.aligned;" ::: "memory"); \
    asm volatile("barrier.cluster.wait.aligned;" ::: "memory"); \
} while (0)

// ---------------------------------------------------------------------------
// tcgen05 / TMA helpers (only in the compute_103a device pass)
// ---------------------------------------------------------------------------
#if HAS_TC
__device__ __forceinline__ uint64_t make_desc(uint32_t addr) {
    const uint64_t base = (uint64_t(2) << 61) | (uint64_t(1) << 46)
                        | (uint64_t(64) << 32) | (uint64_t(1) << 16);
    return base | ((uint64_t)(addr >> 4) & 0x3FFF);
}

#define TC_ALLOC_CG2(sa, n) \
    asm volatile("tcgen05.alloc.cta_group::2.sync.aligned.shared::cta.b32 [%0], %1;" \
                 :: "r"(sa), "r"(n) : "memory")
#define TC_RELINQ_CG2() \
    asm volatile("tcgen05.relinquish_alloc_permit.cta_group::2.sync.aligned;")
#define TC_DEALLOC_CG2(t, n) \
    asm volatile("tcgen05.dealloc.cta_group::2.sync.aligned.b32 %0, %1;" :: "r"(t), "r"(n))
#define TC_COMMIT_MC2(mb) \
    asm volatile("tcgen05.commit.cta_group::2.mbarrier::arrive::one.shared::cluster.multicast::cluster.b64 [%0], %1;" \
                 :: "r"(mb), "h"((uint16_t)3) : "memory")
#define TC_FENCE_AFTER()  asm volatile("tcgen05.fence::after_thread_sync;" ::: "memory")
#define TC_FENCE_BEFORE() asm volatile("tcgen05.fence::before_thread_sync;" ::: "memory")
#define TC_WAIT_LD()      asm volatile("tcgen05.wait::ld.sync.aligned;" ::: "memory")

// cg2 TMA: both CTAs execute; complete_tx targets leader (bit24 cleared) barrier
#define TMA_CG2(sa, mp, cx, cy, mb) \
    asm volatile("{\n\t.reg .b32 lb;\n\t" \
        "and.b32 lb, %4, 0xFEFFFFFF;\n\t" \
        "cp.async.bulk.tensor.3d.cta_group::2.shared::cluster.global.tile.mbarrier::complete_tx::bytes " \
        "[%0], [%1, {%2, %3, %5}], [lb];\n\t}" \
        :: "r"(sa), "l"(mp), "r"(cx), "r"(cy), "r"(mb), "r"(0) : "memory")

#define TC_LD_X32(r, ta) \
    asm volatile( \
        "tcgen05.ld.sync.aligned.32x32b.x32.b32 " \
        "{%0, %1, %2, %3, %4, %5, %6, %7, " \
        " %8, %9, %10, %11, %12, %13, %14, %15, " \
        " %16, %17, %18, %19, %20, %21, %22, %23, " \
        " %24, %25, %26, %27, %28, %29, %30, %31}, [%32];" \
        : "=r"((r)[0]),  "=r"((r)[1]),  "=r"((r)[2]),  "=r"((r)[3]), \
          "=r"((r)[4]),  "=r"((r)[5]),  "=r"((r)[6]),  "=r"((r)[7]), \
          "=r"((r)[8]),  "=r"((r)[9]),  "=r"((r)[10]), "=r"((r)[11]), \
          "=r"((r)[12]), "=r"((r)[13]), "=r"((r)[14]), "=r"((r)[15]), \
          "=r"((r)[16]), "=r"((r)[17]), "=r"((r)[18]), "=r"((r)[19]), \
          "=r"((r)[20]), "=r"((r)[21]), "=r"((r)[22]), "=r"((r)[23]), \
          "=r"((r)[24]), "=r"((r)[25]), "=r"((r)[26]), "=r"((r)[27]), \
          "=r"((r)[28]), "=r"((r)[29]), "=r"((r)[30]), "=r"((r)[31]) \
        : "r"(ta))

__device__ __forceinline__ void mma_ss_cg2(uint32_t d, uint64_t ad, uint64_t bd,
                                           uint32_t idesc, bool acc) {
    uint32_t en = acc ? 1u : 0u;
    asm volatile(
        "{\n\t.reg .pred p;\n\t"
        "setp.ne.u32 p, %5, 0;\n\t"
        "tcgen05.mma.cta_group::2.kind::f16 [%0], %1, %2, %3, "
        "{%4, %4, %4, %4, %4, %4, %4, %4}, p;\n\t}"
        :: "r"(d), "l"(ad), "l"(bd), "r"(idesc), "r"(0u), "r"(en)
        : "memory");
}

// idesc: dtype=F32, atype=btype=BF16, N=128, M=256
#define IDESC ((1u << 4) | (1u << 7) | (1u << 10) | ((TN / 8) << 17) | (16u << 24))

#define FULL_B(s) (sb + (s) * 8)
#define DONE_B(s) (sb + 24 + (s) * 8)

__device__ __forceinline__ void issue_chunk(uint32_t tmem, uint32_t stp32, bool first) {
    uint64_t dAh = make_desc(stp32 + A_HI_OFF);
    uint64_t dAl = make_desc(stp32 + A_LO_OFF);
    uint64_t dBh = make_desc(stp32 + B_HI_OFF);
    uint64_t dBl = make_desc(stp32 + B_LO_OFF);
    #pragma unroll
    for (int k = 0; k < 4; ++k) {
        mma_ss_cg2(tmem, dAh + 2 * k, dBh + 2 * k, IDESC, !(first && k == 0));
        mma_ss_cg2(tmem, dAh + 2 * k, dBl + 2 * k, IDESC, true);
        mma_ss_cg2(tmem, dAl + 2 * k, dBh + 2 * k, IDESC, true);
    }
}

// TMA-fed cg2 mainloop. tid0 (both ranks) = TMA issuer; rank0 tid32 = MMA
// consumer. full[s]: count 1 on rank0 (expect_tx 2*STAGE_BYTES per phase;
// complete_tx from both CTAs' cg2 TMA). done[s]: count 1, multicast commit.
template <int NCHUNKS, typename FT>
__device__ __forceinline__ void cg2_tma_mainloop(uint32_t sb, int tid,
                                                 uint32_t rank, uint32_t tmem,
                                                 FT&& issue_tma) {
    if (tid == 0) {
        for (int c = 0; c < NCHUNKS; ++c) {
            int s = c % NSTAGE;
            if (c >= NSTAGE) MBAR_WAIT(DONE_B(s), (c / NSTAGE - 1) & 1);
            if (rank == 0) MBAR_EXPECT(FULL_B(s), 2 * STAGE_BYTES);
            issue_tma(c, sb + 1024 + s * STAGE_BYTES, FULL_B(s));
        }
        const int lc = NCHUNKS - 1;
        MBAR_WAIT(DONE_B(lc % NSTAGE), (lc / NSTAGE) & 1);
    } else if (rank == 0 && tid == 32) {
        for (int c = 0; c < NCHUNKS; ++c) {
            int s = c % NSTAGE;
            int u = c / NSTAGE;
            uint32_t stp32 = sb + 1024 + s * STAGE_BYTES;
            MBAR_WAIT(FULL_B(s), u & 1);
            issue_chunk(tmem, stp32, c == 0);
            TC_COMMIT_MC2(DONE_B(s));
        }
    }
    __syncthreads();          // everyone held until tid0 confirms last done
    TC_FENCE_AFTER();
}
#endif  // HAS_TC

// ---------------------------------------------------------------------------
// Pre-pass: split x into bf16 hi/lo
// ---------------------------------------------------------------------------
__global__ void split_x_kernel(const float* __restrict__ x) {
    int i = blockIdx.x * blockDim.x + threadIdx.x;
    float4 v = ((const float4*)x)[i];
    __nv_bfloat16 h[4], l[4];
    split2(v.x, h[0], l[0]); split2(v.y, h[1], l[1]);
    split2(v.z, h[2], l[2]); split2(v.w, h[3], l[3]);
    *(uint2*)&g_x_hi[(size_t)i * 4] = *(uint2*)h;
    *(uint2*)&g_x_lo[(size_t)i * 4] = *(uint2*)l;
}

// ---------------------------------------------------------------------------
// Pre-pass: transpose + split weights.  src [e][R][C] fp32 -> dst [e][C][R] bf16
// ---------------------------------------------------------------------------
__global__ void tsplit_kernel(const float* __restrict__ src, int R, int C, int which) {
    __shared__ float tile[32][33];
    int e = blockIdx.z;
    int r0 = blockIdx.y * 32, c0 = blockIdx.x * 32;
    int tx = threadIdx.x, ty = threadIdx.y;          // 32 x 8
    const float* s = src + (size_t)e * R * C;
    #pragma unroll
    for (int i = 0; i < 4; ++i)
        tile[ty + i * 8][tx] = s[(size_t)(r0 + ty + i * 8) * C + c0 + tx];
    __syncthreads();
    __nv_bfloat16* dh = (which ? g_w2t_hi : g_w1t_hi) + (size_t)e * R * C;
    __nv_bfloat16* dl = (which ? g_w2t_lo : g_w1t_lo) + (size_t)e * R * C;
    #pragma unroll
    for (int i = 0; i < 4; ++i) {
        float v = tile[tx][ty + i * 8];
        __nv_bfloat16 h, l;
        split2(v, h, l);
        size_t o = (size_t)(c0 + ty + i * 8) * R + r0 + tx;
        dh[o] = h; dl[o] = l;
    }
}

// ---------------------------------------------------------------------------
// Router: softmax(x @ Wr + br). One warp per token.
// ---------------------------------------------------------------------------
__global__ void router_kernel(const float* __restrict__ x,
                              const float* __restrict__ Wr,
                              const float* __restrict__ br) {
    int warp = (blockIdx.x * blockDim.x + threadIdx.x) >> 5;
    int lane = threadIdx.x & 31;
    if (warp >= NTOK) return;
    const float4* xr = (const float4*)(x + (size_t)warp * DIM);
    const float4* wr = (const float4*)Wr;
    float a0 = 0.f, a1 = 0.f, a2 = 0.f, a3 = 0.f;
    #pragma unroll
    for (int p = 0; p < DIM / 128; ++p) {
        int db = p * 32 + lane;
        float4 xv = xr[db];
        float4 w;
        w = wr[db * 4 + 0];
        a0 += xv.x * w.x; a1 += xv.x * w.y; a2 += xv.x * w.z; a3 += xv.x * w.w;
        w = wr[db * 4 + 1];
        a0 += xv.y * w.x; a1 += xv.y * w.y; a2 += xv.y * w.z; a3 += xv.y * w.w;
        w = wr[db * 4 + 2];
        a0 += xv.z * w.x; a1 += xv.z * w.y; a2 += xv.z * w.z; a3 += xv.z * w.w;
        w = wr[db * 4 + 3];
        a0 += xv.w * w.x; a1 += xv.w * w.y; a2 += xv.w * w.z; a3 += xv.w * w.w;
    }
    #pragma unroll
    for (int off = 16; off; off >>= 1) {
        a0 += __shfl_xor_sync(0xffffffffu, a0, off);
        a1 += __shfl_xor_sync(0xffffffffu, a1, off);
        a2 += __shfl_xor_sync(0xffffffffu, a2, off);
        a3 += __shfl_xor_sync(0xffffffffu, a3, off);
    }
    if (lane == 0) {
        a0 += br[0]; a1 += br[1]; a2 += br[2]; a3 += br[3];
        float m = fmaxf(fmaxf(a0, a1), fmaxf(a2, a3));
        float e0 = expf(a0 - m), e1 = expf(a1 - m), e2 = expf(a2 - m), e3 = expf(a3 - m);
        float inv = 1.0f / (e0 + e1 + e2 + e3);
        *(float4*)&g_w[warp * NE] = make_float4(e0 * inv, e1 * inv, e2 * inv, e3 * inv);
    }
}

// ---------------------------------------------------------------------------
// GEMM1: D = x@W1[e] (cg2 M=256 x N=128, TMA-fed, 2 CTAs/SM);
// epilogue h = split(w * gelu(D + b1))
// grid (NTOK/TM=32, HID/TN=16, NE), cluster (2,1,1)
// ---------------------------------------------------------------------------
__global__ __launch_bounds__(256, 2) __cluster_dims__(2, 1, 1)
void gemm1_kernel(const __grid_constant__ CUtensorMap mAh,
                  const __grid_constant__ CUtensorMap mAl,
                  const __grid_constant__ CUtensorMap mBh,
                  const __grid_constant__ CUtensorMap mBl,
                  const float* __restrict__ x, const float* __restrict__ W1,
                  const float* __restrict__ b1)
{
#if HAS_TC
    extern __shared__ __align__(1024) char smem[];
    uint32_t sb = smem_u32(smem);
    int tid = threadIdx.x, wid = tid >> 5, lane = tid & 31;
    uint32_t rank = (uint32_t)(blockIdx.x & 1);
    int e  = blockIdx.z;
    int t0 = blockIdx.x * TM;                        // this CTA's 128 rows
    int n0 = blockIdx.y * TN;                        // cluster's 128 cols

    if (wid == 0) { TC_ALLOC_CG2(sb + 48, TMEM_COLS); TC_RELINQ_CG2(); }
    __syncthreads();
    uint32_t tmem = *(volatile uint32_t*)(smem + 48);
    if (tid == 0) {
        #pragma unroll
        for (int s = 0; s < NSTAGE; ++s) {
            MBAR_INIT(FULL_B(s), 1);
            MBAR_INIT(DONE_B(s), 1);
        }
        FENCE_ASYNC();
    }
    __syncthreads();
    CLUSTER_SYNC_();

    const int arow = t0;
    const int brow = e * HID + n0 + (int)rank * (TN / 2);

    cg2_tma_mainloop<DIM / TK>(sb, tid, rank, tmem,
        [&](int c, uint32_t stp32, uint32_t mb) {
            int k0 = c * TK;
            TMA_CG2(stp32 + A_HI_OFF, &mAh, k0, arow, mb);
            TMA_CG2(stp32 + A_LO_OFF, &mAl, k0, arow, mb);
            TMA_CG2(stp32 + B_HI_OFF, &mBh, k0, brow, mb);
            TMA_CG2(stp32 + B_LO_OFF, &mBl, k0, brow, mb);
        });

    if (wid < 4) {
        int t = t0 + wid * 32 + lane;
        float w = g_w[t * NE + e];
        const float* b1e = b1 + (size_t)e * HID + n0;
        __nv_bfloat16* hh = g_h_hi + ((size_t)e * NTOK + t) * HID + n0;
        __nv_bfloat16* hl = g_h_lo + ((size_t)e * NTOK + t) * HID + n0;
        #pragma unroll
        for (int g = 0; g < TN / 32; ++g) {
            uint32_t d[32];
            TC_LD_X32(d, tmem + g * 32);
            TC_WAIT_LD();
            __align__(16) __nv_bfloat16 tH[32], tL[32];
            #pragma unroll
            for (int j = 0; j < 32; ++j) {
                float v = __uint_as_float(d[j]) + b1e[g * 32 + j];
                v = gelu_exact(v) * w;
                split2(v, tH[j], tL[j]);
            }
            #pragma unroll
            for (int q = 0; q < 4; ++q) {
                ((uint4*)(hh + g * 32))[q] = ((uint4*)tH)[q];
                ((uint4*)(hl + g * 32))[q] = ((uint4*)tL)[q];
            }
        }
        TC_FENCE_BEFORE();
    }
    __syncthreads();
    if (wid == 0) TC_DEALLOC_CG2(tmem, TMEM_COLS);
    CLUSTER_SYNC_();
#else
    const int e  = blockIdx.z;
    const int t0 = blockIdx.x * TM;
    const float* A = x;
    const float* B = W1 + (size_t)e * DIM * HID;
    float* C = g_h32 + (size_t)e * NTOK * HID;

    __shared__ float As[BK][BM];
    __shared__ float Bs[BK][BN];
    const int tid = threadIdx.x;
    const int tx = tid & 15, ty = tid >> 4;

    {
        const int n0 = blockIdx.y * TN;
        unsigned long long acc[8][4];
        #pragma unroll
        for (int i = 0; i < 8; ++i)
            #pragma unroll
            for (int p = 0; p < 4; ++p) acc[i][p] = 0ull;

        for (int kk = 0; kk < DIM; kk += BK) {
            #pragma unroll
            for (int f = 0; f < 2; ++f) {
                int idx = tid + f * 256;
                int row = idx >> 2, q = idx & 3;
                float4 v = *(const float4*)(A + (size_t)(t0 + row) * DIM + kk + q * 4);
                As[q * 4 + 0][row] = v.x; As[q * 4 + 1][row] = v.y;
                As[q * 4 + 2][row] = v.z; As[q * 4 + 3][row] = v.w;
            }
            #pragma unroll
            for (int f = 0; f < 2; ++f) {
                int idx = tid + f * 256;
                int kr = idx >> 5, q = idx & 31;
                *(float4*)&Bs[kr][q * 4] =
                    *(const float4*)(B + (size_t)(kk + kr) * HID + n0 + q * 4);
            }
            __syncthreads();
            #pragma unroll
            for (int k = 0; k < BK; ++k) {
                float4 av0 = *(const float4*)&As[k][ty * 4];
                float4 av1 = *(const float4*)&As[k][ty * 4 + 64];
                ulonglong2 bq0 = *(const ulonglong2*)&Bs[k][tx * 4];
                ulonglong2 bq1 = *(const ulonglong2*)&Bs[k][tx * 4 + 64];
                unsigned long long bp[4] = {bq0.x, bq0.y, bq1.x, bq1.y};
                float a_s[8] = {av0.x, av0.y, av0.z, av0.w, av1.x, av1.y, av1.z, av1.w};
                unsigned long long ad[8];
                #pragma unroll
                for (int i = 0; i < 8; ++i) ad[i] = dup2(a_s[i]);
                #pragma unroll
                for (int i = 0; i < 8; ++i)
                    #pragma unroll
                    for (int p = 0; p < 4; ++p)
                        FFMA2(acc[i][p], ad[i], bp[p]);
            }
            __syncthreads();
        }

        const float* brow = b1 + (size_t)e * HID;
        #pragma unroll
        for (int i = 0; i < 8; ++i) {
            int gr = t0 + ty * 4 + (i & 3) + ((i >> 2) << 6);
            float* crow = C + (size_t)gr * HID;
            #pragma unroll
            for (int p = 0; p < 4; ++p) {
                int gc = n0 + tx * 4 + ((p >> 1) << 6) + ((p & 1) << 1);
                float lo = __uint_as_float((unsigned int)acc[i][p]);
                float hi = __uint_as_float((unsigned int)(acc[i][p] >> 32));
                crow[gc]     = gelu_exact(lo + brow[gc]);
                crow[gc + 1] = gelu_exact(hi + brow[gc + 1]);
            }
        }
        __syncthreads();
    }
#endif
}

// ---------------------------------------------------------------------------
// GEMM2: D = sum_e (w.h[e]) @ W2[e] (cg2 M=256 x N=128, TMA-fed);
// out = D + sum_e w_e b2[e]
// grid (NTOK/TM=32, DIM/TN=8), cluster (2,1,1)
// ---------------------------------------------------------------------------
__global__ __launch_bounds__(256, 2) __cluster_dims__(2, 1, 1)
void gemm2_kernel(const __grid_constant__ CUtensorMap mAh,
                  const __grid_constant__ CUtensorMap mAl,
                  const __grid_constant__ CUtensorMap mBh,
                  const __grid_constant__ CUtensorMap mBl,
                  const float* __restrict__ W2, const float* __restrict__ b2,
                  float* __restrict__ out)
{
#if HAS_TC
    extern __shared__ __align__(1024) char smem[];
    uint32_t sb = smem_u32(smem);
    int tid = threadIdx.x, wid = tid >> 5, lane = tid & 31;
    uint32_t rank = (uint32_t)(blockIdx.x & 1);
    int t0 = blockIdx.x * TM;
    int n0 = blockIdx.y * TN;

    if (wid == 0) { TC_ALLOC_CG2(sb + 48, TMEM_COLS); TC_RELINQ_CG2(); }
    __syncthreads();
    uint32_t tmem = *(volatile uint32_t*)(smem + 48);
    if (tid == 0) {
        #pragma unroll
        for (int s = 0; s < NSTAGE; ++s) {
            MBAR_INIT(FULL_B(s), 1);
            MBAR_INIT(DONE_B(s), 1);
        }
        FENCE_ASYNC();
    }
    __syncthreads();
    CLUSTER_SYNC_();

    cg2_tma_mainloop<NE * HID / TK>(sb, tid, rank, tmem,
        [&](int c, uint32_t stp32, uint32_t mb) {
            int e  = c >> 5;
            int k0 = (c & 31) * TK;
            int ar = e * NTOK + t0;
            int br = e * DIM + n0 + (int)rank * (TN / 2);
            TMA_CG2(stp32 + A_HI_OFF, &mAh, k0, ar, mb);
            TMA_CG2(stp32 + A_LO_OFF, &mAl, k0, ar, mb);
            TMA_CG2(stp32 + B_HI_OFF, &mBh, k0, br, mb);
            TMA_CG2(stp32 + B_LO_OFF, &mBl, k0, br, mb);
        });

    if (wid < 4) {
        int t = t0 + wid * 32 + lane;
        float4 w4 = *(const float4*)&g_w[t * NE];
        float* orow = out + (size_t)t * DIM + n0;
        #pragma unroll
        for (int g = 0; g < TN / 32; ++g) {
            uint32_t d[32];
            TC_LD_X32(d, tmem + g * 32);
            TC_WAIT_LD();
            __align__(16) float tO[32];
            #pragma unroll
            for (int j = 0; j < 32; ++j) {
                int n = n0 + g * 32 + j;
                float bias = w4.x * b2[n] + w4.y * b2[DIM + n]
                           + w4.z * b2[2 * DIM + n] + w4.w * b2[3 * DIM + n];
                tO[j] = __uint_as_float(d[j]) + bias;
            }
            #pragma unroll
            for (int q = 0; q < 8; ++q)
                ((uint4*)(orow + g * 32))[q] = ((uint4*)tO)[q];
        }
        TC_FENCE_BEFORE();
    }
    __syncthreads();
    if (wid == 0) TC_DEALLOC_CG2(tmem, TMEM_COLS);
    CLUSTER_SYNC_();
#else
    const int t0 = blockIdx.x * TM;
    __shared__ float As[BK][BM];
    __shared__ float Bs[BK][BN];
    __shared__ float ws[BM];
    const int tid = threadIdx.x;
    const int tx = tid & 15, ty = tid >> 4;

    {
        const int n0 = blockIdx.y * TN;
        unsigned long long acc[8][4];
        #pragma unroll
        for (int i = 0; i < 8; ++i)
            #pragma unroll
            for (int p = 0; p < 4; ++p) acc[i][p] = 0ull;

        for (int e = 0; e < NE; ++e) {
            if (tid < BM) ws[tid] = g_w[(t0 + tid) * NE + e];
            __syncthreads();
            const float* A = g_h32 + (size_t)e * NTOK * HID;
            const float* B = W2 + (size_t)e * HID * DIM;

            for (int kk = 0; kk < HID; kk += BK) {
                #pragma unroll
                for (int f = 0; f < 2; ++f) {
                    int idx = tid + f * 256;
                    int row = idx >> 2, q = idx & 3;
                    float wv = ws[row];
                    float4 v = *(const float4*)(A + (size_t)(t0 + row) * HID + kk + q * 4);
                    As[q * 4 + 0][row] = v.x * wv; As[q * 4 + 1][row] = v.y * wv;
                    As[q * 4 + 2][row] = v.z * wv; As[q * 4 + 3][row] = v.w * wv;
                }
                #pragma unroll
                for (int f = 0; f < 2; ++f) {
                    int idx = tid + f * 256;
                    int kr = idx >> 5, q = idx & 31;
                    *(float4*)&Bs[kr][q * 4] =
                        *(const float4*)(B + (size_t)(kk + kr) * DIM + n0 + q * 4);
                }
                __syncthreads();
                #pragma unroll
                for (int k = 0; k < BK; ++k) {
                    float4 av0 = *(const float4*)&As[k][ty * 4];
                    float4 av1 = *(const float4*)&As[k][ty * 4 + 64];
                    ulonglong2 bq0 = *(const ulonglong2*)&Bs[k][tx * 4];
                    ulonglong2 bq1 = *(const ulonglong2*)&Bs[k][tx * 4 + 64];
                    unsigned long long bp[4] = {bq0.x, bq0.y, bq1.x, bq1.y};
                    float a_s[8] = {av0.x, av0.y, av0.z, av0.w, av1.x, av1.y, av1.z, av1.w};
                    unsigned long long ad[8];
                    #pragma unroll
                    for (int i = 0; i < 8; ++i) ad[i] = dup2(a_s[i]);
                    #pragma unroll
                    for (int i = 0; i < 8; ++i)
                        #pragma unroll
                        for (int p = 0; p < 4; ++p)
                            FFMA2(acc[i][p], ad[i], bp[p]);
                }
                __syncthreads();
            }
        }

        #pragma unroll
        for (int i = 0; i < 8; ++i) {
            int gr = t0 + ty * 4 + (i & 3) + ((i >> 2) << 6);
            float4 wv = *(const float4*)&g_w[gr * NE];
            float* crow = out + (size_t)gr * DIM;
            #pragma unroll
            for (int p = 0; p < 4; ++p) {
                int gc = n0 + tx * 4 + ((p >> 1) << 6) + ((p & 1) << 1);
                float lo = __uint_as_float((unsigned int)acc[i][p]);
                float hi = __uint_as_float((unsigned int)(acc[i][p] >> 32));
                float blo = wv.x * b2[0 * DIM + gc] + wv.y * b2[1 * DIM + gc]
                          + wv.z * b2[2 * DIM + gc] + wv.w * b2[3 * DIM + gc];
                float bhi = wv.x * b2[0 * DIM + gc + 1] + wv.y * b2[1 * DIM + gc + 1]
                          + wv.z * b2[2 * DIM + gc + 1] + wv.w * b2[3 * DIM + gc + 1];
                crow[gc]     = lo + blo;
                crow[gc + 1] = hi + bhi;
            }
        }
        __syncthreads();
    }
#endif
}

// ---------------------------------------------------------------------------
// Host-side tensormap construction (runtime entry point, no -lcuda link)
// ---------------------------------------------------------------------------
typedef CUresult (*EncodeFn)(CUtensorMap*, CUtensorMapDataType, cuuint32_t, void*,
    const cuuint64_t*, const cuuint64_t*, const cuuint32_t*, const cuuint32_t*,
    CUtensorMapInterleave, CUtensorMapSwizzle, CUtensorMapL2promotion,
    CUtensorMapFloatOOBfill);

static EncodeFn get_encode_fn() {
    static EncodeFn fn = nullptr;
    if (!fn) {
        void* p = nullptr;
        cudaDriverEntryPointQueryResult qr;
#if CUDART_VERSION >= 12050
        cudaGetDriverEntryPointByVersion("cuTensorMapEncodeTiled", &p, 12000,
                                         cudaEnableDefault, &qr);
#else
        cudaGetDriverEntryPoint("cuTensorMapEncodeTiled", &p,
                                cudaEnableDefault, &qr);
#endif
        fn = (EncodeFn)p;
    }
    return fn;
}

static void encode_map(CUtensorMap* m, void* ptr, uint64_t d0, uint64_t d1,
                       uint32_t b0, uint32_t b1) {
    cuuint64_t dims[3] = {d0, d1, 1};
    cuuint64_t strides[2] = {d0 * 2, d0 * 2 * d1};
    cuuint32_t box[3] = {b0, b1, 1};
    cuuint32_t es[3] = {1, 1, 1};
    get_encode_fn()(m, CU_TENSOR_MAP_DATA_TYPE_BFLOAT16, 3, ptr, dims, strides,
                    box, es, CU_TENSOR_MAP_INTERLEAVE_NONE,
                    CU_TENSOR_MAP_SWIZZLE_128B, CU_TENSOR_MAP_L2_PROMOTION_L2_128B,
                    CU_TENSOR_MAP_FLOAT_OOB_FILL_NONE);
}

// ---------------------------------------------------------------------------
extern "C" void kernel_launch(void* const* d_in, const int* in_sizes, int n_in,
                              void* d_out, int out_size) {
    const float* x  = (const float*)d_in[0];
    const float* W1 = (const float*)d_in[1];
    const float* b1 = (const float*)d_in[2];
    const float* W2 = (const float*)d_in[3];
    const float* b2 = (const float*)d_in[4];
    const float* Wr = (const float*)d_in[5];
    const float* br = (const float*)d_in[6];
    float* out = (float*)d_out;

    cudaFuncSetAttribute(gemm1_kernel, cudaFuncAttributeMaxDynamicSharedMemorySize, SMEM_BYTES);
    cudaFuncSetAttribute(gemm2_kernel, cudaFuncAttributeMaxDynamicSharedMemorySize, SMEM_BYTES);

    // Static side streams + events (created once, outside any graph capture:
    // the first call is the un-captured correctness run).
    static cudaStream_t s1 = nullptr, s2 = nullptr, s3 = nullptr;
    static cudaEvent_t  e0, e1, e2, e3;
    if (!s1) {
        cudaStreamCreateWithFlags(&s1, cudaStreamNonBlocking);
        cudaStreamCreateWithFlags(&s2, cudaStreamNonBlocking);
        cudaStreamCreateWithFlags(&s3, cudaStreamNonBlocking);
        cudaEventCreateWithFlags(&e0, cudaEventDisableTiming);
        cudaEventCreateWithFlags(&e1, cudaEventDisableTiming);
        cudaEventCreateWithFlags(&e2, cudaEventDisableTiming);
        cudaEventCreateWithFlags(&e3, cudaEventDisableTiming);
    }

    void *p_xh, *p_xl, *p_w1h, *p_w1l, *p_w2h, *p_w2l, *p_hh, *p_hl;
    cudaGetSymbolAddress(&p_xh, g_x_hi);
    cudaGetSymbolAddress(&p_xl, g_x_lo);
    cudaGetSymbolAddress(&p_w1h, g_w1t_hi);
    cudaGetSymbolAddress(&p_w1l, g_w1t_lo);
    cudaGetSymbolAddress(&p_w2h, g_w2t_hi);
    cudaGetSymbolAddress(&p_w2l, g_w2t_lo);
    cudaGetSymbolAddress(&p_hh, g_h_hi);
    cudaGetSymbolAddress(&p_hl, g_h_lo);

    CUtensorMap m1Ah, m1Al, m1Bh, m1Bl, m2Ah, m2Al, m2Bh, m2Bl;
    encode_map(&m1Ah, p_xh, DIM, NTOK, TK, TM);
    encode_map(&m1Al, p_xl, DIM, NTOK, TK, TM);
    encode_map(&m1Bh, p_w1h, DIM, (uint64_t)NE * HID, TK, TN / 2);
    encode_map(&m1Bl, p_w1l, DIM, (uint64_t)NE * HID, TK, TN / 2);
    encode_map(&m2Ah, p_hh, HID, (uint64_t)NE * NTOK, TK, TM);
    encode_map(&m2Al, p_hl, HID, (uint64_t)NE * NTOK, TK, TM);
    encode_map(&m2Bh, p_w2h, HID, (uint64_t)NE * DIM, TK, TN / 2);
    encode_map(&m2Bl, p_w2l, HID, (uint64_t)NE * DIM, TK, TN / 2);

    // Fork: prepasses run concurrently on side streams; tsplit-W2 also
    // overlaps gemm1. Join edges give gemm1 {split_x, tsplit-W1} (+ router
    // in-stream) and gemm2 {tsplit-W2}.
    cudaEventRecord(e0, 0);
    cudaStreamWaitEvent(s1, e0, 0);
    cudaStreamWaitEvent(s2, e0, 0);
    cudaStreamWaitEvent(s3, e0, 0);

    router_kernel<<<NTOK / 8, 256, 0, 0>>>(x, Wr, br);
    split_x_kernel<<<NTOK * DIM / 1024, 256, 0, s1>>>(x);
    {   // W1 [E][DIM][HID] -> W1T [E][HID][DIM]
        dim3 g(HID / 32, DIM / 32, NE), b(32, 8);
        tsplit_kernel<<<g, b, 0, s2>>>(W1, DIM, HID, 0);
    }
    {   // W2 [E][HID][DIM] -> W2T [E][DIM][HID]  (overlaps gemm1)
        dim3 g(DIM / 32, HID / 32, NE), b(32, 8);
        tsplit_kernel<<<g, b, 0, s3>>>(W2, HID, DIM, 1);
    }
    cudaEventRecord(e1, s1);
    cudaEventRecord(e2, s2);
    cudaEventRecord(e3, s3);
    cudaStreamWaitEvent(0, e1, 0);
    cudaStreamWaitEvent(0, e2, 0);
    {
        dim3 g(NTOK / TM, HID / TN, NE);     // 32 x 16 x 4, clusters of 2 on x
        gemm1_kernel<<<g, 256, SMEM_BYTES, 0>>>(m1Ah, m1Al, m1Bh, m1Bl, x, W1, b1);
    }
    cudaStreamWaitEvent(0, e3, 0);
    {
        dim3 g(NTOK / TM, DIM / TN);         // 32 x 8, clusters of 2 on x
        gemm2_kernel<<<g, 256, SMEM_BYTES, 0>>>(m2Ah, m2Al, m2Bh, m2Bl, W2, b2, out);
    }
}